// round 2
// baseline (speedup 1.0000x reference)
#include <cuda_runtime.h>
#include <cuda_bf16.h>

// Problem constants
#define BB   16      // batch
#define CI   32      // in channels
#define CO   32      // out channels
#define DD   32      // input D=H=W
#define DO   30      // output D=H=W (valid conv, K=3)
#define NQ   512     // query length
#define TAPS 27      // 3^3
#define NW   (CO * CI * TAPS)   // 27648 weights per sample

// Tiling for conv kernel
#define COG  8       // out-channels per block
#define ZT   8       // z outputs per block
#define YT   8       // y outputs per block

// Per-sample conv weights scratch: [b][co][ci][27]
__device__ float g_weights[BB * NW];

// ---------------------------------------------------------------------------
// Stage 1: weights[b, j] = sum_q query[b, q] * lut[q, j]
// Each thread owns 2 consecutive j (float2 loads of lut), all 16 batches.
// Grid: 27648 / (128*2) = 108 blocks of 128 threads.
// Memory-bound on the 56 MB lookup table (~10-15 us floor).
// ---------------------------------------------------------------------------
__global__ void weights_kernel(const float* __restrict__ query,
                               const float* __restrict__ lut) {
    __shared__ float sq[BB * NQ];   // 32 KB
    int tid = threadIdx.x;
    for (int i = tid; i < BB * NQ; i += blockDim.x) sq[i] = query[i];
    __syncthreads();

    int j = (blockIdx.x * blockDim.x + tid) * 2;

    float2 acc[BB];
#pragma unroll
    for (int b = 0; b < BB; b++) acc[b] = make_float2(0.f, 0.f);

    for (int q = 0; q < NQ; q++) {
        float2 l = *reinterpret_cast<const float2*>(lut + (size_t)q * NW + j);
#pragma unroll
        for (int b = 0; b < BB; b++) {
            float qv = sq[b * NQ + q];
            acc[b].x = fmaf(qv, l.x, acc[b].x);
            acc[b].y = fmaf(qv, l.y, acc[b].y);
        }
    }
#pragma unroll
    for (int b = 0; b < BB; b++) {
        g_weights[b * NW + j]     = acc[b].x;
        g_weights[b * NW + j + 1] = acc[b].y;
    }
}

// ---------------------------------------------------------------------------
// Stage 2: direct conv3d, per-sample weights.
// Block: (32, 8) threads; tx -> x, ty -> y within an 8-wide y tile.
// Each thread accumulates COG=8 out-channels x ZT=8 z outputs in registers.
// Inner loop per tap: 8 LDS (w, broadcast) + 8 LDS (v) -> 64 FMA.
// Smem: weights 8co x 32ci x 27 (27.6 KB) + input tile [10][10][32] (12.8 KB).
// Grid: (16 tiles = 4 zt x 4 yt, 4 co-groups, 16 batches) = 1024 blocks.
// ---------------------------------------------------------------------------
__global__ void __launch_bounds__(256, 2)
conv_kernel(const float* __restrict__ target, float* __restrict__ out) {
    __shared__ float sW[COG * CI * TAPS];                              // 6912 floats
    __shared__ __align__(16) float sIn[(ZT + 2) * (YT + 2) * DD + 4]; // 3204 floats

    const int tx  = threadIdx.x;          // 0..31 -> x
    const int ty  = threadIdx.y;          // 0..7  -> local y
    const int tid = ty * 32 + tx;

    const int tile = blockIdx.x;          // 0..15
    const int zt   = tile >> 2;
    const int yt   = tile & 3;
    const int cog  = blockIdx.y;          // 0..3
    const int b    = blockIdx.z;          // 0..15

    const int z0 = zt * ZT;
    const int y0 = yt * YT;

    // Load this block's weight slice: [8 co][32 ci][27]
    const float* wsrc = g_weights + (size_t)b * NW + (size_t)cog * (COG * CI * TAPS);
    for (int i = tid; i < COG * CI * TAPS; i += 256) sW[i] = wsrc[i];

    float acc[COG][ZT];
#pragma unroll
    for (int c = 0; c < COG; c++)
#pragma unroll
        for (int z = 0; z < ZT; z++) acc[c][z] = 0.f;

    const float* tb = target + (size_t)b * CI * DD * DD * DD;

    for (int ci = 0; ci < CI; ci++) {
        __syncthreads();   // protect previous iteration's sIn reads (and sW on iter 0)
        // Cooperative float4 load of input tile [10 z][10 y][32 x],
        // zero-padded at y/z edges (padding predicate is per-row, so rows
        // vectorize cleanly: 800 LDG.128 instead of 3200 LDG.32).
        const float* src = tb + (size_t)ci * DD * DD * DD;
        for (int i = tid; i < (ZT + 2) * (YT + 2) * (DD / 4); i += 256) {
            int row = i >> 3;             // / 8 float4 per row
            int xq  = i & 7;
            int zz  = row / (YT + 2);
            int yy  = row - zz * (YT + 2);
            int gz = z0 + zz, gy = y0 + yy;
            float4 v = make_float4(0.f, 0.f, 0.f, 0.f);
            if (gz < DD && gy < DD)
                v = *reinterpret_cast<const float4*>(src + (gz * DD + gy) * DD + xq * 4);
            *reinterpret_cast<float4*>(sIn + row * DD + xq * 4) = v;
        }
        __syncthreads();

        const float* wci = sW + ci * TAPS;
#pragma unroll
        for (int kz = 0; kz < 3; kz++)
#pragma unroll
            for (int ky = 0; ky < 3; ky++)
#pragma unroll
                for (int kx = 0; kx < 3; kx++) {
                    const int t = (kz * 3 + ky) * 3 + kx;
                    float w[COG];
#pragma unroll
                    for (int c = 0; c < COG; c++)
                        w[c] = wci[c * (CI * TAPS) + t];   // smem broadcast
                    float v[ZT];
#pragma unroll
                    for (int z = 0; z < ZT; z++)
                        v[z] = sIn[((z + kz) * (YT + 2) + (ty + ky)) * DD + tx + kx];
#pragma unroll
                    for (int c = 0; c < COG; c++)
#pragma unroll
                        for (int z = 0; z < ZT; z++)
                            acc[c][z] = fmaf(w[c], v[z], acc[c][z]);
                }
    }

    // Store valid outputs (x-halo garbage lives only in discarded tx>=30 lanes)
    const int y = y0 + ty;
    if (tx < DO && y < DO) {
#pragma unroll
        for (int c = 0; c < COG; c++) {
            const int co = cog * COG + c;
            float* obase = out + (((size_t)(b * CO + co)) * DO) * DO * DO + y * DO + tx;
#pragma unroll
            for (int z = 0; z < ZT; z++) {
                const int gz = z0 + z;
                if (gz < DO)
                    obase[(size_t)gz * DO * DO] = acc[c][z];
            }
        }
    }
}

// ---------------------------------------------------------------------------
// Launch
// ---------------------------------------------------------------------------
extern "C" void kernel_launch(void* const* d_in, const int* in_sizes, int n_in,
                              void* d_out, int out_size) {
    const float* query  = nullptr;
    const float* target = nullptr;
    const float* lut    = nullptr;
    for (int i = 0; i < n_in; i++) {
        if (in_sizes[i] == BB * NQ)                     query  = (const float*)d_in[i];
        else if (in_sizes[i] == BB * CI * DD * DD * DD) target = (const float*)d_in[i];
        else if (in_sizes[i] == NQ * NW)                lut    = (const float*)d_in[i];
    }

    // Stage 1: per-sample conv weights
    weights_kernel<<<NW / (128 * 2), 128>>>(query, lut);

    // Stage 2: conv
    dim3 grid(16 /* 4 zt x 4 yt */, CO / COG, BB);
    dim3 block(32, 8);
    conv_kernel<<<grid, block>>>(target, (float*)d_out);
}

// round 5
// speedup vs baseline: 1.2612x; 1.2612x over previous
#include <cuda_runtime.h>
#include <cuda_bf16.h>

// Problem constants
#define BB   16      // batch
#define CI   32      // in channels
#define CO   32      // out channels
#define DD   32      // input D=H=W
#define DO   30      // output D=H=W (valid conv, K=3)
#define NQ   512     // query length
#define TAPS 27      // 3^3
#define NW   (CO * CI * TAPS)   // 27648 weights per sample

// Conv tiling
#define COG  8       // out-channels per block
#define ZT   4       // z outputs per block
#define YT   8       // y outputs per block
// block: 16 x-pairs (covers x 0..31 packed) x 8 y = 128 threads

__device__ float g_weights[BB * NW];   // [b][co][ci][27]

// ---------------------------------------------------------------------------
// f32x2 packed-FMA helpers (Blackwell sm_100+).
// fma.rn.f32x2 takes untyped .b64 operands -> must use "l" constraints
// (u64 regs), NOT "d" (f64 regs) — ptxas rejects the latter.
// ---------------------------------------------------------------------------
typedef unsigned long long u64;

__device__ __forceinline__ void fma2(u64& d, u64 a, u64 b) {
    asm("fma.rn.f32x2 %0, %1, %2, %0;" : "+l"(d) : "l"(a), "l"(b));
}
__device__ __forceinline__ u64 dup2(float w) {
    u64 r;
    asm("mov.b64 %0, {%1, %1};" : "=l"(r) : "f"(w));   // {w, w}
    return r;
}
// middle pair {lo = A.hi (x1), hi = C.lo (x2)}
__device__ __forceinline__ u64 mid2(u64 A, u64 C) {
    return (A >> 32) | (C << 32);
}

// ---------------------------------------------------------------------------
// Stage 1: weights[b, j] = sum_q query[b, q] * lut[q, j]
// 216 blocks x 128 threads, 1 column j per thread, q unrolled x8 for MLP.
// ---------------------------------------------------------------------------
__global__ void __launch_bounds__(128)
weights_kernel(const float* __restrict__ query, const float* __restrict__ lut) {
    __shared__ float sq[BB * NQ];   // 32 KB
    const int tid = threadIdx.x;
    for (int i = tid; i < BB * NQ; i += 128) sq[i] = query[i];
    __syncthreads();

    const int j = blockIdx.x * 128 + tid;   // 216*128 = 27648 exactly

    float acc[BB];
#pragma unroll
    for (int b = 0; b < BB; b++) acc[b] = 0.f;

    for (int q = 0; q < NQ; q += 8) {
        float l[8];
#pragma unroll
        for (int u = 0; u < 8; u++)
            l[u] = __ldg(lut + (size_t)(q + u) * NW + j);
#pragma unroll
        for (int u = 0; u < 8; u++) {
#pragma unroll
            for (int b = 0; b < BB; b++)
                acc[b] = fmaf(sq[b * NQ + q + u], l[u], acc[b]);
        }
    }
#pragma unroll
    for (int b = 0; b < BB; b++) g_weights[b * NW + j] = acc[b];
}

// ---------------------------------------------------------------------------
// Stage 2: direct conv3d with packed f32x2 FMAs.
// Thread (tx, ty): x-pair (2tx, 2tx+1), y = y0+ty.
// Accumulators: 8 co x 4 z packed pairs = 32 u64.
// Per tap: v pairs A=[x0,x1], C=[x2,x3] via ld.shared.b64; kx=1 operand
// recombined from A/C halves (no extra LDS). w duplicated via one mov.b64.
// ---------------------------------------------------------------------------
__global__ void __launch_bounds__(128, 4)
conv_kernel(const float* __restrict__ target, float* __restrict__ out) {
    __shared__ float sW[COG * CI * TAPS];                               // 27648 B
    __shared__ __align__(16) float sIn[(ZT + 2) * (YT + 2) * DD + 4];   // 7696 B

    const int tx  = threadIdx.x;          // 0..15 -> x pair
    const int ty  = threadIdx.y;          // 0..7  -> local y
    const int tid = ty * 16 + tx;

    const int zt  = blockIdx.x >> 2;      // 0..7
    const int yt  = blockIdx.x & 3;       // 0..3
    const int cog = blockIdx.y;           // 0..3
    const int b   = blockIdx.z;           // 0..15

    const int z0 = zt * ZT;
    const int y0 = yt * YT;

    // Weight slice [8 co][32 ci][27]
    const float* wsrc = g_weights + (size_t)b * NW + (size_t)cog * (COG * CI * TAPS);
    for (int i = tid; i < COG * CI * TAPS; i += 128) sW[i] = wsrc[i];

    u64 acc[COG][ZT];
#pragma unroll
    for (int c = 0; c < COG; c++)
#pragma unroll
        for (int z = 0; z < ZT; z++) acc[c][z] = 0ull;   // {0.f, 0.f}

    const float* tb = target + (size_t)b * CI * DD * DD * DD;

    for (int ci = 0; ci < CI; ci++) {
        __syncthreads();   // protect previous iteration's sIn (and sW on iter 0)
        // Stage input tile [6 z][10 y][32 x] as float4 rows, zero-padded edges
        const float* src = tb + (size_t)ci * DD * DD * DD;
        for (int i = tid; i < (ZT + 2) * (YT + 2) * (DD / 4); i += 128) {
            int row = i >> 3;
            int xq  = i & 7;
            int zz  = row / (YT + 2);
            int yy  = row - zz * (YT + 2);
            int gz = z0 + zz, gy = y0 + yy;
            float4 v = make_float4(0.f, 0.f, 0.f, 0.f);
            if (gz < DD && gy < DD)
                v = *reinterpret_cast<const float4*>(src + (gz * DD + gy) * DD + xq * 4);
            *reinterpret_cast<float4*>(sIn + row * DD + xq * 4) = v;
        }
        __syncthreads();

        const float* wci = sW + ci * TAPS;
#pragma unroll
        for (int kz = 0; kz < 3; kz++) {
#pragma unroll
            for (int ky = 0; ky < 3; ky++) {
                // v operands for this (kz,ky): per z, pairs at kx=0,1,2
                u64 V0[ZT], V1[ZT], V2[ZT];
#pragma unroll
                for (int z = 0; z < ZT; z++) {
                    const float* p = sIn + ((z + kz) * (YT + 2) + (ty + ky)) * DD + 2 * tx;
                    u64 A = *reinterpret_cast<const u64*>(p);       // x0,x1
                    u64 C = *reinterpret_cast<const u64*>(p + 2);   // x2,x3
                    V0[z] = A;
                    V2[z] = C;
                    V1[z] = mid2(A, C);                             // x1,x2
                }
                const int tbase = (kz * 3 + ky) * 3;
#pragma unroll
                for (int c = 0; c < COG; c++) {
                    const float* wc = wci + c * (CI * TAPS) + tbase;
                    u64 w0 = dup2(wc[0]);
                    u64 w1 = dup2(wc[1]);
                    u64 w2 = dup2(wc[2]);
#pragma unroll
                    for (int z = 0; z < ZT; z++) {
                        fma2(acc[c][z], w0, V0[z]);
                        fma2(acc[c][z], w1, V1[z]);
                        fma2(acc[c][z], w2, V2[z]);
                    }
                }
            }
        }
    }

    // Store: x-pairs (2tx, 2tx+1); DO=30 -> tx 0..14 fully valid, tx=15 fully out
    const int y = y0 + ty;
    if (tx < 15 && y < DO) {
#pragma unroll
        for (int c = 0; c < COG; c++) {
            const int co = cog * COG + c;
#pragma unroll
            for (int z = 0; z < ZT; z++) {
                const int gz = z0 + z;
                if (gz < DO) {
                    size_t idx = ((((size_t)(b * CO + co)) * DO + gz) * DO + y) * DO + 2 * tx;
                    *reinterpret_cast<u64*>(out + idx) = acc[c][z];   // 8B aligned (even idx)
                }
            }
        }
    }
}

// ---------------------------------------------------------------------------
// Launch
// ---------------------------------------------------------------------------
extern "C" void kernel_launch(void* const* d_in, const int* in_sizes, int n_in,
                              void* d_out, int out_size) {
    const float* query  = nullptr;
    const float* target = nullptr;
    const float* lut    = nullptr;
    for (int i = 0; i < n_in; i++) {
        if (in_sizes[i] == BB * NQ)                     query  = (const float*)d_in[i];
        else if (in_sizes[i] == BB * CI * DD * DD * DD) target = (const float*)d_in[i];
        else if (in_sizes[i] == NQ * NW)                lut    = (const float*)d_in[i];
    }

    weights_kernel<<<NW / 128, 128>>>(query, lut);

    dim3 grid(32 /* 8 zt x 4 yt */, CO / COG, BB);
    dim3 block(16, 8);
    conv_kernel<<<grid, block>>>(target, (float*)d_out);
}